// round 1
// baseline (speedup 1.0000x reference)
#include <cuda_runtime.h>

#define S_LEN 512
#define BATCH 8
#define HEADS 8
#define DHEAD 64
#define INDIM 512
#define PH    322                 // 5*D + 2
#define PROJ  (HEADS * PH)        // 2576
#define MROWS (S_LEN * BATCH)     // 4096

// ---- scratch (static device memory; no allocation at runtime) ----
__device__ float g_normed[MROWS * INDIM];   // 8 MB
__device__ float g_qkvb[MROWS * PROJ];      // 42 MB
__device__ float g_hs[MROWS * INDIM];       // 8 MB

// ============================================================
// Kernel 1: LayerNorm (biased var, eps=1e-5)
// grid = 4096, block = 256 (2 elements / thread)
// ============================================================
__global__ void __launch_bounds__(256) ln_kernel(
    const float* __restrict__ x,
    const float* __restrict__ gamma,
    const float* __restrict__ beta)
{
    int m = blockIdx.x;
    int t = threadIdx.x;
    const float* row = x + (size_t)m * INDIM;
    float v0 = row[t];
    float v1 = row[t + 256];

    float s = v0 + v1;
    #pragma unroll
    for (int o = 16; o; o >>= 1) s += __shfl_xor_sync(0xffffffffu, s, o);

    __shared__ float red[8];
    __shared__ float red2[8];
    int w = t >> 5, lane = t & 31;
    if (lane == 0) red[w] = s;
    __syncthreads();
    float tot = 0.f;
    #pragma unroll
    for (int i = 0; i < 8; i++) tot += red[i];
    float mean = tot * (1.0f / INDIM);

    float d0 = v0 - mean, d1 = v1 - mean;
    float sq = d0 * d0 + d1 * d1;
    #pragma unroll
    for (int o = 16; o; o >>= 1) sq += __shfl_xor_sync(0xffffffffu, sq, o);
    if (lane == 0) red2[w] = sq;
    __syncthreads();
    float vtot = 0.f;
    #pragma unroll
    for (int i = 0; i < 8; i++) vtot += red2[i];
    float inv = rsqrtf(vtot * (1.0f / INDIM) + 1e-5f);

    g_normed[(size_t)m * INDIM + t]       = d0 * inv * gamma[t]       + beta[t];
    g_normed[(size_t)m * INDIM + t + 256] = d1 * inv * gamma[t + 256] + beta[t + 256];
}

// ============================================================
// Kernel 2/5: fp32 SGEMM, C = A * B^T (both row-major, K-contig)
// BM=BN=128, BK=16, 256 threads, 8x8 outputs per thread.
// RESID: C = A*B^T + resid (for output projection + residual).
// M divisible by 128, K divisible by 16; N guarded.
// ============================================================
template<bool RESID>
__global__ void __launch_bounds__(256) sgemm_nt(
    const float* __restrict__ A,
    const float* __restrict__ Bm,
    float* __restrict__ C,
    const float* __restrict__ resid,
    int Ndim, int Kdim)
{
    const int BM = 128, BN = 128, BK = 16;
    __shared__ float As[BK][BM + 4];   // +4 pad: keeps 16B alignment, kills STS conflicts
    __shared__ float Bs[BK][BN + 4];

    int tid   = threadIdx.x;
    int mBase = blockIdx.y * BM;
    int nBase = blockIdx.x * BN;
    int tx = tid & 15, ty = tid >> 4;

    int lrow = tid >> 2;          // 0..63
    int lcol = (tid & 3) * 4;     // 0,4,8,12 (float offset within BK)

    float acc[8][8];
    #pragma unroll
    for (int i = 0; i < 8; i++)
        #pragma unroll
        for (int j = 0; j < 8; j++) acc[i][j] = 0.f;

    for (int k0 = 0; k0 < Kdim; k0 += BK) {
        #pragma unroll
        for (int it = 0; it < 2; it++) {
            int row = lrow + it * 64;
            float4 a = *reinterpret_cast<const float4*>(
                A + (size_t)(mBase + row) * Kdim + k0 + lcol);
            As[lcol + 0][row] = a.x; As[lcol + 1][row] = a.y;
            As[lcol + 2][row] = a.z; As[lcol + 3][row] = a.w;

            int nrow = nBase + row;
            float4 bv = make_float4(0.f, 0.f, 0.f, 0.f);
            if (nrow < Ndim)
                bv = *reinterpret_cast<const float4*>(
                    Bm + (size_t)nrow * Kdim + k0 + lcol);
            Bs[lcol + 0][row] = bv.x; Bs[lcol + 1][row] = bv.y;
            Bs[lcol + 2][row] = bv.z; Bs[lcol + 3][row] = bv.w;
        }
        __syncthreads();

        #pragma unroll
        for (int kk = 0; kk < BK; kk++) {
            float4 a0 = *reinterpret_cast<const float4*>(&As[kk][ty * 8]);
            float4 a1 = *reinterpret_cast<const float4*>(&As[kk][ty * 8 + 4]);
            float4 b0 = *reinterpret_cast<const float4*>(&Bs[kk][tx * 8]);
            float4 b1 = *reinterpret_cast<const float4*>(&Bs[kk][tx * 8 + 4]);
            float af[8] = {a0.x, a0.y, a0.z, a0.w, a1.x, a1.y, a1.z, a1.w};
            float bf[8] = {b0.x, b0.y, b0.z, b0.w, b1.x, b1.y, b1.z, b1.w};
            #pragma unroll
            for (int i = 0; i < 8; i++)
                #pragma unroll
                for (int j = 0; j < 8; j++)
                    acc[i][j] = fmaf(af[i], bf[j], acc[i][j]);
        }
        __syncthreads();
    }

    #pragma unroll
    for (int i = 0; i < 8; i++) {
        int gm = mBase + ty * 8 + i;
        #pragma unroll
        for (int j = 0; j < 8; j++) {
            int gn = nBase + tx * 8 + j;
            if (gn < Ndim) {
                float v = acc[i][j];
                if (RESID) v += resid[(size_t)gm * Ndim + gn];
                C[(size_t)gm * Ndim + gn] = v;
            }
        }
    }
}

// ============================================================
// Kernel 3: per-head activations in place on g_qkvb
// softmax over q[0:64], k[64:128], rk[192:256]; sigmoid beta/rbeta.
// grid = 4096, block = 256 (warp w = head w, 2 elems/lane/segment)
// ============================================================
__global__ void __launch_bounds__(256) act_kernel()
{
    int m    = blockIdx.x;
    int wp   = threadIdx.x >> 5;   // head index
    int lane = threadIdx.x & 31;
    float* base = g_qkvb + (size_t)m * PROJ + wp * PH;

    const int segs[3] = {0, 64, 192};
    #pragma unroll
    for (int si = 0; si < 3; si++) {
        int seg = segs[si];
        float a  = base[seg + lane];
        float bb = base[seg + 32 + lane];
        float mx = fmaxf(a, bb);
        #pragma unroll
        for (int o = 16; o; o >>= 1) mx = fmaxf(mx, __shfl_xor_sync(0xffffffffu, mx, o));
        float ea = __expf(a - mx);
        float eb = __expf(bb - mx);
        float s2 = ea + eb;
        #pragma unroll
        for (int o = 16; o; o >>= 1) s2 += __shfl_xor_sync(0xffffffffu, s2, o);
        float inv = 1.0f / s2;
        base[seg + lane]      = ea * inv;
        base[seg + 32 + lane] = eb * inv;
    }
    if (lane < 2) {
        float v = base[320 + lane];
        base[320 + lane] = 1.0f / (1.0f + __expf(-v));
    }
}

// ============================================================
// Kernel 4: sequential scan (delta-rule fast weight + fast RNN)
// 64 blocks = (b,h) pairs; 128 threads; thread pair (2i,2i+1) owns row i,
// halves c=0/1 of W[i][:] and R[i][:] in registers (32 floats each).
// Inputs double-buffered in SMEM with prefetch; 3 barriers/step.
// ============================================================
__device__ __forceinline__ float dot32(const float* a, const float* __restrict__ b)
{
    float s0 = 0.f, s1 = 0.f, s2 = 0.f, s3 = 0.f;
    #pragma unroll
    for (int j = 0; j < 32; j += 4) {
        s0 = fmaf(a[j],     b[j],     s0);
        s1 = fmaf(a[j + 1], b[j + 1], s1);
        s2 = fmaf(a[j + 2], b[j + 2], s2);
        s3 = fmaf(a[j + 3], b[j + 3], s3);
    }
    return (s0 + s1) + (s2 + s3);
}

__global__ void __launch_bounds__(128) scan_kernel()
{
    int bh = blockIdx.x;
    int b = bh >> 3, h = bh & 7;
    int t = threadIdx.x;
    int i = t >> 1;       // matrix row 0..63
    int c = t & 1;        // column half
    int w = t >> 5;

    __shared__ float buf[2][PH];
    __shared__ float h_sh[64];
    __shared__ float e_sh[64];
    __shared__ float red[4];

    float W[32], R[32];
    #pragma unroll
    for (int j = 0; j < 32; j++) { W[j] = 0.f; R[j] = 0.f; }

    {   // preload step 0
        const float* src = g_qkvb + (size_t)b * PROJ + h * PH;
        buf[0][t]       = src[t];
        buf[0][t + 128] = src[t + 128];
        if (t < PH - 256) buf[0][t + 256] = src[t + 256];
    }
    if (t < 64) h_sh[t] = 0.f;
    __syncthreads();

    for (int s = 0; s < S_LEN; s++) {
        const float* in = buf[s & 1];

        // prefetch next step's inputs into registers
        float p0 = 0.f, p1 = 0.f, p2 = 0.f;
        if (s + 1 < S_LEN) {
            const float* src = g_qkvb + (size_t)((s + 1) * BATCH + b) * PROJ + h * PH;
            p0 = src[t];
            p1 = src[t + 128];
            if (t < PH - 256) p2 = src[t + 256];
        }

        // ---- softmax(h_prev) phase A: max ----
        float hv = h_sh[t & 63];
        float mx = hv;
        #pragma unroll
        for (int o = 16; o; o >>= 1) mx = fmaxf(mx, __shfl_xor_sync(0xffffffffu, mx, o));
        if ((t & 31) == 0 && w < 2) red[w] = mx;
        __syncthreads();                                  // bar1

        // ---- softmax phase B: exp + sum partials ----
        float gmx = fmaxf(red[0], red[1]);
        float ev = __expf(hv - gmx);
        float sm = ev;
        #pragma unroll
        for (int o = 16; o; o >>= 1) sm += __shfl_xor_sync(0xffffffffu, sm, o);
        if (w < 2) {
            e_sh[t] = ev;
            if ((t & 31) == 0) red[2 + w] = sm;
        }

        // ---- delta-rule fast weight W (independent of softmax) ----
        float betav = in[320];
        float kreg[32];
        const float* kp = in + 64 + c * 32;
        #pragma unroll
        for (int j = 0; j < 32; j++) kreg[j] = kp[j];

        float vold = dot32(W, kreg);
        vold += __shfl_xor_sync(0xffffffffu, vold, 1);
        float coef = betav * (in[128 + i] - vold);
        #pragma unroll
        for (int j = 0; j < 32; j++) W[j] = fmaf(coef, kreg[j], W[j]);

        float z = dot32(W, in + c * 32);                  // q segment
        z += __shfl_xor_sync(0xffffffffu, z, 1);
        __syncthreads();                                  // bar2

        // ---- fast RNN: R update + h = z + R softmax(h_prev) ----
        float invTot = 1.0f / (red[2] + red[3]);
        float rbetav = in[321];
        float rkreg[32];
        const float* rkp = in + 192 + c * 32;
        #pragma unroll
        for (int j = 0; j < 32; j++) rkreg[j] = rkp[j];

        float voldR = dot32(R, rkreg);
        voldR += __shfl_xor_sync(0xffffffffu, voldR, 1);
        float coefR = rbetav * (in[256 + i] - voldR);
        #pragma unroll
        for (int j = 0; j < 32; j++) R[j] = fmaf(coefR, rkreg[j], R[j]);

        float hd = dot32(R, e_sh + c * 32);
        hd += __shfl_xor_sync(0xffffffffu, hd, 1);
        float hn = z + hd * invTot;

        if (c == 0) {
            h_sh[i] = hn;
            g_hs[(size_t)(s * BATCH + b) * INDIM + h * DHEAD + i] = hn;
        }

        // commit prefetched inputs
        float* nb = buf[(s & 1) ^ 1];
        nb[t]       = p0;
        nb[t + 128] = p1;
        if (t < PH - 256) nb[t + 256] = p2;
        __syncthreads();                                  // bar3
    }
}

// ============================================================
// Launch
// ============================================================
extern "C" void kernel_launch(void* const* d_in, const int* in_sizes, int n_in,
                              void* d_out, int out_size)
{
    const float* x      = (const float*)d_in[0];
    const float* W_slow = (const float*)d_in[1];
    const float* W_out  = (const float*)d_in[2];
    const float* gamma  = (const float*)d_in[3];
    const float* betap  = (const float*)d_in[4];
    float* out = (float*)d_out;

    float *p_normed = nullptr, *p_qkvb = nullptr, *p_hs = nullptr;
    cudaGetSymbolAddress((void**)&p_normed, g_normed);
    cudaGetSymbolAddress((void**)&p_qkvb,   g_qkvb);
    cudaGetSymbolAddress((void**)&p_hs,     g_hs);

    // 1. LayerNorm
    ln_kernel<<<MROWS, 256>>>(x, gamma, betap);

    // 2. qkvb = normed @ W_slow^T   (M=4096, N=2576, K=512)
    {
        dim3 grid((PROJ + 127) / 128, MROWS / 128);
        sgemm_nt<false><<<grid, 256>>>(p_normed, W_slow, p_qkvb, nullptr, PROJ, INDIM);
    }

    // 3. softmax / sigmoid activations in place
    act_kernel<<<MROWS, 256>>>();

    // 4. sequential scan -> g_hs
    scan_kernel<<<BATCH * HEADS, 128>>>();

    // 5. out = x + hs @ W_out^T     (M=4096, N=512, K=512)
    {
        dim3 grid(INDIM / 128, MROWS / 128);
        sgemm_nt<true><<<grid, 256>>>(p_hs, W_out, out, x, INDIM, HEADS * DHEAD);
    }
}